// round 8
// baseline (speedup 1.0000x reference)
#include <cuda_runtime.h>
#include <cuda_bf16.h>
#include <mma.h>
#include <cstdint>

using namespace nvcuda;

#define N_NODES 50000
#define N_EDGES 800000
#define DIM 128
#define NLAYERS 3
#define NBLK_NODE 196            // ceil(50000/256)
#define GEMM_BLOCKS 391          // ceil(50000/128)
#define AGG_BLOCKS 6250          // ceil(50000/8)  (8 nodes per 256-thread block)
#define EDGE_BLOCKS 3125         // ceil(800000/256)

// ---------------------------------------------------------------------------
// Scratch (no allocations allowed -> __device__ globals)
// ---------------------------------------------------------------------------
__device__ float g_h[N_NODES * DIM];
__device__ float g_agg[N_NODES * DIM];
__device__ float g_part[N_NODES * DIM];
__device__ int   g_deg[N_NODES];
__device__ int   g_off[N_NODES + 1];
__device__ int   g_cur[N_NODES];
__device__ int   g_srcs[N_EDGES];
__device__ int   g_bsum[256];
__device__ int   g_bbase[256];

// ---------------------------------------------------------------------------
// bf16 hi/lo split of a pair of floats, packed as bf16x2 words
// ---------------------------------------------------------------------------
__device__ __forceinline__ void split2(float a0, float a1, uint32_t& hi, uint32_t& lo) {
    __nv_bfloat16 h0 = __float2bfloat16(a0);
    __nv_bfloat16 h1 = __float2bfloat16(a1);
    float r0 = a0 - __bfloat162float(h0);
    float r1 = a1 - __bfloat162float(h1);
    __nv_bfloat16 l0 = __float2bfloat16(r0);
    __nv_bfloat16 l1 = __float2bfloat16(r1);
    hi = (uint32_t)__bfloat16_as_ushort(h0) | ((uint32_t)__bfloat16_as_ushort(h1) << 16);
    lo = (uint32_t)__bfloat16_as_ushort(l0) | ((uint32_t)__bfloat16_as_ushort(l1) << 16);
}

// Staging buffer offsets (bytes)
#define A_HI 0
#define A_LO 10240
#define W_HI 20480
#define W_LO 29184
#define STAGE_BYTES 37888   // also reused as 8 warps x 16x68 fp32 epilogue scratch

// ---------------------------------------------------------------------------
// GEMM body: 128x128 CTA tile, K=128, bf16x3 split, 8 warps as 4(m) x 2(n).
//   EP=0 (infc): out = A@W + bias
//   EP=1 (root): out = A@W + bias            (partial, no relu)
//   EP=2 (rel) : out = relu(A@W + part) + hres
// ---------------------------------------------------------------------------
template <int EP>
__device__ __forceinline__ void gemm_body(
    const float* __restrict__ A, const float* __restrict__ W,
    const float* __restrict__ bias, const float* __restrict__ part,
    const float* __restrict__ hres, float* __restrict__ out,
    int row0, char* smem_raw)
{
    const int tid  = threadIdx.x;
    const int wid  = tid >> 5;
    const int lane = tid & 31;
    const int wm   = wid & 3;
    const int wn   = wid >> 2;

    wmma::fragment<wmma::accumulator, 16, 16, 16, float> acc[2][4];
#pragma unroll
    for (int mi = 0; mi < 2; mi++)
#pragma unroll
        for (int ni = 0; ni < 4; ni++)
            wmma::fill_fragment(acc[mi][ni], 0.0f);

    for (int kc = 0; kc < 4; kc++) {
        const int k0 = kc * 32;
        __syncthreads();
#pragma unroll
        for (int t = 0; t < 4; t++) {
            int q  = tid + t * 256;
            int r  = q >> 3;
            int c4 = q & 7;
            int gr = row0 + r;
            float4 v = make_float4(0.f, 0.f, 0.f, 0.f);
            if (gr < N_NODES)
                v = *reinterpret_cast<const float4*>(A + (size_t)gr * DIM + k0 + c4 * 4);
            uint32_t h0, l0, h1, l1;
            split2(v.x, v.y, h0, l0);
            split2(v.z, v.w, h1, l1);
            uint32_t boff = (uint32_t)r * 80u + (uint32_t)c4 * 8u;
            *reinterpret_cast<uint2*>(smem_raw + A_HI + boff) = make_uint2(h0, h1);
            *reinterpret_cast<uint2*>(smem_raw + A_LO + boff) = make_uint2(l0, l1);
        }
#pragma unroll
        for (int t = 0; t < 4; t++) {
            int q  = tid + t * 256;
            int kk = q >> 5;
            int c4 = q & 31;
            float4 v = *reinterpret_cast<const float4*>(W + (size_t)(k0 + kk) * DIM + c4 * 4);
            uint32_t h0, l0, h1, l1;
            split2(v.x, v.y, h0, l0);
            split2(v.z, v.w, h1, l1);
            uint32_t boff = (uint32_t)kk * 272u + (uint32_t)c4 * 8u;
            *reinterpret_cast<uint2*>(smem_raw + W_HI + boff) = make_uint2(h0, h1);
            *reinterpret_cast<uint2*>(smem_raw + W_LO + boff) = make_uint2(l0, l1);
        }
        __syncthreads();

#pragma unroll
        for (int ks = 0; ks < 2; ks++) {
            wmma::fragment<wmma::matrix_a, 16, 16, 16, __nv_bfloat16, wmma::row_major> ah[2], al[2];
#pragma unroll
            for (int mi = 0; mi < 2; mi++) {
                const __nv_bfloat16* pa_hi = reinterpret_cast<const __nv_bfloat16*>(smem_raw + A_HI)
                                           + (wm * 32 + mi * 16) * 40 + ks * 16;
                const __nv_bfloat16* pa_lo = reinterpret_cast<const __nv_bfloat16*>(smem_raw + A_LO)
                                           + (wm * 32 + mi * 16) * 40 + ks * 16;
                wmma::load_matrix_sync(ah[mi], pa_hi, 40);
                wmma::load_matrix_sync(al[mi], pa_lo, 40);
            }
#pragma unroll
            for (int ni = 0; ni < 4; ni++) {
                wmma::fragment<wmma::matrix_b, 16, 16, 16, __nv_bfloat16, wmma::row_major> bh, bl;
                const __nv_bfloat16* pb_hi = reinterpret_cast<const __nv_bfloat16*>(smem_raw + W_HI)
                                           + (ks * 16) * 136 + wn * 64 + ni * 16;
                const __nv_bfloat16* pb_lo = reinterpret_cast<const __nv_bfloat16*>(smem_raw + W_LO)
                                           + (ks * 16) * 136 + wn * 64 + ni * 16;
                wmma::load_matrix_sync(bh, pb_hi, 136);
                wmma::load_matrix_sync(bl, pb_lo, 136);
#pragma unroll
                for (int mi = 0; mi < 2; mi++) {
                    wmma::mma_sync(acc[mi][ni], ah[mi], bh, acc[mi][ni]);
                    wmma::mma_sync(acc[mi][ni], ah[mi], bl, acc[mi][ni]);
                    wmma::mma_sync(acc[mi][ni], al[mi], bh, acc[mi][ni]);
                }
            }
        }
    }

    __syncthreads();
    float* sc = reinterpret_cast<float*>(smem_raw) + wid * (16 * 68);
    const int col0 = wn * 64;
    const int rl   = lane >> 1;
    const int half = lane & 1;
#pragma unroll
    for (int mi = 0; mi < 2; mi++) {
#pragma unroll
        for (int ni = 0; ni < 4; ni++)
            wmma::store_matrix_sync(sc + ni * 16, acc[mi][ni], 68, wmma::mem_row_major);
        __syncwarp();
        int grow = row0 + wm * 32 + mi * 16 + rl;
        if (grow < N_NODES) {
#pragma unroll
            for (int j = 0; j < 8; j++) {
                int c = half * 32 + j * 4;
                float4 v = *reinterpret_cast<const float4*>(sc + rl * 68 + c);
                if (EP == 0 || EP == 1) {
                    float4 b4 = *reinterpret_cast<const float4*>(bias + col0 + c);
                    v.x += b4.x; v.y += b4.y; v.z += b4.z; v.w += b4.w;
                } else {
                    float4 p4 = *reinterpret_cast<const float4*>(part + (size_t)grow * DIM + col0 + c);
                    v.x += p4.x; v.y += p4.y; v.z += p4.z; v.w += p4.w;
                    v.x = fmaxf(v.x, 0.f); v.y = fmaxf(v.y, 0.f);
                    v.z = fmaxf(v.z, 0.f); v.w = fmaxf(v.w, 0.f);
                    float4 r4 = *reinterpret_cast<const float4*>(hres + (size_t)grow * DIM + col0 + c);
                    v.x += r4.x; v.y += r4.y; v.z += r4.z; v.w += r4.w;
                }
                *reinterpret_cast<float4*>(out + (size_t)grow * DIM + col0 + c) = v;
            }
        }
        __syncwarp();
    }
}

// ---------------------------------------------------------------------------
// Aggregate body: one warp per node; coalesced index load + shfl broadcast,
// 4 neighbor rows in flight (MLP=4).
// ---------------------------------------------------------------------------
__device__ __forceinline__ void agg_body(const float* __restrict__ hin, int ablk) {
    const int tid  = threadIdx.x;
    const int node = ablk * 8 + (tid >> 5);
    const int lane = tid & 31;
    if (node >= N_NODES) return;
    const int s = g_off[node];
    const int e = g_off[node + 1];
    const float4* __restrict__ h4 = reinterpret_cast<const float4*>(hin);
    float4 acc = make_float4(0.f, 0.f, 0.f, 0.f);
    int i = s;
    while (i < e) {
        int cnt = min(e - i, 32);
        int idx = (lane < cnt) ? g_srcs[i + lane] : 0;
        int j = 0;
        for (; j + 4 <= cnt; j += 4) {
            int s0 = __shfl_sync(0xFFFFFFFFu, idx, j);
            int s1 = __shfl_sync(0xFFFFFFFFu, idx, j + 1);
            int s2 = __shfl_sync(0xFFFFFFFFu, idx, j + 2);
            int s3 = __shfl_sync(0xFFFFFFFFu, idx, j + 3);
            float4 v0 = h4[(size_t)s0 * 32 + lane];
            float4 v1 = h4[(size_t)s1 * 32 + lane];
            float4 v2 = h4[(size_t)s2 * 32 + lane];
            float4 v3 = h4[(size_t)s3 * 32 + lane];
            acc.x += (v0.x + v1.x) + (v2.x + v3.x);
            acc.y += (v0.y + v1.y) + (v2.y + v3.y);
            acc.z += (v0.z + v1.z) + (v2.z + v3.z);
            acc.w += (v0.w + v1.w) + (v2.w + v3.w);
        }
        for (; j < cnt; j++) {
            int s0 = __shfl_sync(0xFFFFFFFFu, idx, j);
            float4 v0 = h4[(size_t)s0 * 32 + lane];
            acc.x += v0.x; acc.y += v0.y; acc.z += v0.z; acc.w += v0.w;
        }
        i += cnt;
    }
    reinterpret_cast<float4*>(g_agg)[(size_t)node * 32 + lane] = acc;
}

// ---------------------------------------------------------------------------
// Kernels
// ---------------------------------------------------------------------------
__global__ __launch_bounds__(256) void gemm_infc_kernel(
    const float* __restrict__ A, const float* __restrict__ W,
    const float* __restrict__ bias, float* __restrict__ out)
{
    __shared__ __align__(16) char smem_raw[STAGE_BYTES];
    gemm_body<0>(A, W, bias, nullptr, nullptr, out, blockIdx.x * 128, smem_raw);
}

// Heterogeneous: blocks [0,GEMM_BLOCKS) -> part = h@Wroot + b; rest -> gather
__global__ __launch_bounds__(256) void layer_k1_kernel(
    const float* __restrict__ h, const float* __restrict__ Wroot,
    const float* __restrict__ brel, float* __restrict__ part)
{
    __shared__ __align__(16) char smem_raw[STAGE_BYTES];
    if (blockIdx.x < GEMM_BLOCKS) {
        gemm_body<1>(h, Wroot, brel, nullptr, nullptr, part, blockIdx.x * 128, smem_raw);
    } else {
        agg_body(h, blockIdx.x - GEMM_BLOCKS);
    }
}

__global__ __launch_bounds__(256) void layer_k2_kernel(
    const float* __restrict__ Wrel, const float* __restrict__ h,
    float* __restrict__ out)
{
    __shared__ __align__(16) char smem_raw[STAGE_BYTES];
    gemm_body<2>(g_agg, Wrel, nullptr, g_part, h, out, blockIdx.x * 128, smem_raw);
}

// ---------------------------------------------------------------------------
// CSR construction: histogram -> hierarchical scan -> fill
// ---------------------------------------------------------------------------
__global__ void zero_deg_kernel() {
    int i = blockIdx.x * blockDim.x + threadIdx.x;
    if (i < N_NODES) g_deg[i] = 0;
}

__global__ void hist_kernel(const int* __restrict__ dst) {
    int e = blockIdx.x * blockDim.x + threadIdx.x;
    if (e < N_EDGES) atomicAdd(&g_deg[dst[e]], 1);
}

__global__ void block_reduce_kernel() {
    __shared__ int sh[256];
    int tid = threadIdx.x;
    int i = blockIdx.x * 256 + tid;
    int v = (i < N_NODES) ? g_deg[i] : 0;
    sh[tid] = v;
    __syncthreads();
#pragma unroll
    for (int s = 128; s > 0; s >>= 1) {
        if (tid < s) sh[tid] += sh[tid + s];
        __syncthreads();
    }
    if (tid == 0) g_bsum[blockIdx.x] = sh[0];
}

__global__ void scan_bsum_kernel() {
    __shared__ int sh[256];
    int tid = threadIdx.x;
    int v = (tid < NBLK_NODE) ? g_bsum[tid] : 0;
    sh[tid] = v;
    __syncthreads();
#pragma unroll
    for (int off = 1; off < 256; off <<= 1) {
        int t = (tid >= off) ? sh[tid - off] : 0;
        __syncthreads();
        sh[tid] += t;
        __syncthreads();
    }
    if (tid < NBLK_NODE) g_bbase[tid] = sh[tid] - v;
    if (tid == 0) g_off[N_NODES] = N_EDGES;
}

__global__ void scan_write_kernel() {
    __shared__ int sh[256];
    int tid = threadIdx.x;
    int i = blockIdx.x * 256 + tid;
    int v = (i < N_NODES) ? g_deg[i] : 0;
    sh[tid] = v;
    __syncthreads();
#pragma unroll
    for (int off = 1; off < 256; off <<= 1) {
        int t = (tid >= off) ? sh[tid - off] : 0;
        __syncthreads();
        sh[tid] += t;
        __syncthreads();
    }
    if (i < N_NODES) {
        int o = g_bbase[blockIdx.x] + sh[tid] - v;
        g_off[i] = o;
        g_cur[i] = o;
    }
}

__global__ void fill_kernel(const int* __restrict__ src, const int* __restrict__ dst) {
    int e = blockIdx.x * blockDim.x + threadIdx.x;
    if (e < N_EDGES) {
        int d = dst[e];
        int pos = atomicAdd(&g_cur[d], 1);
        g_srcs[pos] = src[e];
    }
}

// ---------------------------------------------------------------------------
// Launch (CSR chain forked onto a side stream, overlapping in_fc GEMM)
// ---------------------------------------------------------------------------
extern "C" void kernel_launch(void* const* d_in, const int* in_sizes, int n_in,
                              void* d_out, int out_size)
{
    const float* x       = (const float*)d_in[0];
    const int*   ei      = (const int*)  d_in[1];
    const float* in_fc_w = (const float*)d_in[2];
    const float* in_fc_b = (const float*)d_in[3];
    const float* w_rel   = (const float*)d_in[4];
    const float* b_rel   = (const float*)d_in[5];
    const float* w_root  = (const float*)d_in[6];
    float* out = (float*)d_out;

    const int* src = ei;
    const int* dst = ei + N_EDGES;

    float* h_ptr;    cudaGetSymbolAddress((void**)&h_ptr, g_h);
    float* part_ptr; cudaGetSymbolAddress((void**)&part_ptr, g_part);

    static cudaStream_t s2 = nullptr;
    static cudaEvent_t evFork = nullptr, evCSR = nullptr;
    if (s2 == nullptr) {
        cudaStreamCreateWithFlags(&s2, cudaStreamNonBlocking);
        cudaEventCreateWithFlags(&evFork, cudaEventDisableTiming);
        cudaEventCreateWithFlags(&evCSR, cudaEventDisableTiming);
    }

    // Fork: CSR chain on side stream
    cudaEventRecord(evFork, 0);
    cudaStreamWaitEvent(s2, evFork, 0);
    zero_deg_kernel<<<NBLK_NODE, 256, 0, s2>>>();
    hist_kernel<<<EDGE_BLOCKS, 256, 0, s2>>>(dst);
    block_reduce_kernel<<<NBLK_NODE, 256, 0, s2>>>();
    scan_bsum_kernel<<<1, 256, 0, s2>>>();
    scan_write_kernel<<<NBLK_NODE, 256, 0, s2>>>();
    fill_kernel<<<EDGE_BLOCKS, 256, 0, s2>>>(src, dst);
    cudaEventRecord(evCSR, s2);

    // Main stream: in_fc (independent of CSR)
    gemm_infc_kernel<<<GEMM_BLOCKS, 256>>>(x, in_fc_w, in_fc_b, h_ptr);

    // Join before first layer (needs CSR)
    cudaStreamWaitEvent(0, evCSR, 0);

    // 3 GraphConv layers: k1 = (root GEMM || gather), k2 = rel GEMM + epilogue
    for (int l = 0; l < NLAYERS; l++) {
        layer_k1_kernel<<<GEMM_BLOCKS + AGG_BLOCKS, 256>>>(
            h_ptr, w_root + (size_t)l * DIM * DIM, b_rel + (size_t)l * DIM, part_ptr);
        float* dst_buf = (l == NLAYERS - 1) ? out : h_ptr;
        layer_k2_kernel<<<GEMM_BLOCKS, 256>>>(
            w_rel + (size_t)l * DIM * DIM, h_ptr, dst_buf);
    }
}

// round 9
// speedup vs baseline: 1.5321x; 1.5321x over previous
#include <cuda_runtime.h>
#include <cuda_bf16.h>
#include <mma.h>
#include <cstdint>

using namespace nvcuda;

#define N_NODES 50000
#define N_EDGES 800000
#define DIM 128
#define NLAYERS 3
#define NBLK_NODE 196   // ceil(50000/256)

// ---------------------------------------------------------------------------
// Scratch (no allocations allowed -> __device__ globals)
// ---------------------------------------------------------------------------
__device__ float g_h[N_NODES * DIM];
__device__ float g_agg[N_NODES * DIM];
__device__ int   g_deg[N_NODES];
__device__ int   g_off[N_NODES + 1];
__device__ int   g_cur[N_NODES];
__device__ int   g_srcs[N_EDGES];
__device__ int   g_bsum[256];
__device__ int   g_bbase[256];

// ---------------------------------------------------------------------------
// bf16 hi/lo split of a pair of floats, packed as bf16x2 words
// ---------------------------------------------------------------------------
__device__ __forceinline__ void split2(float a0, float a1, uint32_t& hi, uint32_t& lo) {
    __nv_bfloat16 h0 = __float2bfloat16(a0);
    __nv_bfloat16 h1 = __float2bfloat16(a1);
    float r0 = a0 - __bfloat162float(h0);
    float r1 = a1 - __bfloat162float(h1);
    __nv_bfloat16 l0 = __float2bfloat16(r0);
    __nv_bfloat16 l1 = __float2bfloat16(r1);
    hi = (uint32_t)__bfloat16_as_ushort(h0) | ((uint32_t)__bfloat16_as_ushort(h1) << 16);
    lo = (uint32_t)__bfloat16_as_ushort(l0) | ((uint32_t)__bfloat16_as_ushort(l1) << 16);
}

// ---------------------------------------------------------------------------
// WMMA bf16x3 GEMM
//   FUSED=false: out = A1 @ W1 + bias                       (K=128)
//   FUSED=true : out = relu([A1|A2] @ [W1;W2] + bias) + A2  (K=256, resid=A2 rows)
// CTA: 128 rows x 128 cols. 8 warps as 4(m) x 2(n); warp tile 32x64.
// ---------------------------------------------------------------------------
#define A_HI 0
#define A_LO 10240
#define W_HI 20480
#define W_LO 29184
#define SMEM_BYTES 37888   // also reused as 8 warps x 16x68 fp32 epilogue scratch

template <bool FUSED>
__global__ __launch_bounds__(256) void gemm_wmma_kernel(
    const float* __restrict__ A1, const float* __restrict__ W1,
    const float* __restrict__ A2, const float* __restrict__ W2,
    const float* __restrict__ bias, float* __restrict__ out)
{
    __shared__ __align__(16) char smem_raw[SMEM_BYTES];

    const int tid  = threadIdx.x;
    const int wid  = tid >> 5;
    const int lane = tid & 31;
    const int wm   = wid & 3;
    const int wn   = wid >> 2;
    const int row0 = blockIdx.x * 128;

    constexpr int KCAT   = FUSED ? 256 : 128;
    constexpr int NCHUNK = KCAT / 32;

    wmma::fragment<wmma::accumulator, 16, 16, 16, float> acc[2][4];
#pragma unroll
    for (int mi = 0; mi < 2; mi++)
#pragma unroll
        for (int ni = 0; ni < 4; ni++)
            wmma::fill_fragment(acc[mi][ni], 0.0f);

    for (int kc = 0; kc < NCHUNK; kc++) {
        const int k0 = kc * 32;
        __syncthreads();

        // --- stage A chunk ---
#pragma unroll
        for (int t = 0; t < 4; t++) {
            int q  = tid + t * 256;
            int r  = q >> 3;
            int c4 = q & 7;
            int col = k0 + c4 * 4;
            int gr  = row0 + r;
            float4 v = make_float4(0.f, 0.f, 0.f, 0.f);
            if (gr < N_NODES) {
                const float* base = (!FUSED || col < 128) ? A1 : A2;
                int cc = (!FUSED || col < 128) ? col : col - 128;
                v = *reinterpret_cast<const float4*>(base + (size_t)gr * DIM + cc);
            }
            uint32_t h0, l0, h1, l1;
            split2(v.x, v.y, h0, l0);
            split2(v.z, v.w, h1, l1);
            uint32_t boff = (uint32_t)r * 80u + (uint32_t)c4 * 8u;
            *reinterpret_cast<uint2*>(smem_raw + A_HI + boff) = make_uint2(h0, h1);
            *reinterpret_cast<uint2*>(smem_raw + A_LO + boff) = make_uint2(l0, l1);
        }

        // --- stage W chunk ---
#pragma unroll
        for (int t = 0; t < 4; t++) {
            int q  = tid + t * 256;
            int kk = q >> 5;
            int c4 = q & 31;
            int krow = k0 + kk;
            const float* base = (!FUSED || krow < 128) ? W1 : W2;
            int kr = (!FUSED || krow < 128) ? krow : krow - 128;
            float4 v = *reinterpret_cast<const float4*>(base + (size_t)kr * DIM + c4 * 4);
            uint32_t h0, l0, h1, l1;
            split2(v.x, v.y, h0, l0);
            split2(v.z, v.w, h1, l1);
            uint32_t boff = (uint32_t)kk * 272u + (uint32_t)c4 * 8u;
            *reinterpret_cast<uint2*>(smem_raw + W_HI + boff) = make_uint2(h0, h1);
            *reinterpret_cast<uint2*>(smem_raw + W_LO + boff) = make_uint2(l0, l1);
        }
        __syncthreads();

        // --- MMA: 2 k-steps of 16 ---
#pragma unroll
        for (int ks = 0; ks < 2; ks++) {
            wmma::fragment<wmma::matrix_a, 16, 16, 16, __nv_bfloat16, wmma::row_major> ah[2], al[2];
#pragma unroll
            for (int mi = 0; mi < 2; mi++) {
                const __nv_bfloat16* pa_hi = reinterpret_cast<const __nv_bfloat16*>(smem_raw + A_HI)
                                           + (wm * 32 + mi * 16) * 40 + ks * 16;
                const __nv_bfloat16* pa_lo = reinterpret_cast<const __nv_bfloat16*>(smem_raw + A_LO)
                                           + (wm * 32 + mi * 16) * 40 + ks * 16;
                wmma::load_matrix_sync(ah[mi], pa_hi, 40);
                wmma::load_matrix_sync(al[mi], pa_lo, 40);
            }
#pragma unroll
            for (int ni = 0; ni < 4; ni++) {
                wmma::fragment<wmma::matrix_b, 16, 16, 16, __nv_bfloat16, wmma::row_major> bh, bl;
                const __nv_bfloat16* pb_hi = reinterpret_cast<const __nv_bfloat16*>(smem_raw + W_HI)
                                           + (ks * 16) * 136 + wn * 64 + ni * 16;
                const __nv_bfloat16* pb_lo = reinterpret_cast<const __nv_bfloat16*>(smem_raw + W_LO)
                                           + (ks * 16) * 136 + wn * 64 + ni * 16;
                wmma::load_matrix_sync(bh, pb_hi, 136);
                wmma::load_matrix_sync(bl, pb_lo, 136);
#pragma unroll
                for (int mi = 0; mi < 2; mi++) {
                    wmma::mma_sync(acc[mi][ni], ah[mi], bh, acc[mi][ni]);
                    wmma::mma_sync(acc[mi][ni], ah[mi], bl, acc[mi][ni]);
                    wmma::mma_sync(acc[mi][ni], al[mi], bh, acc[mi][ni]);
                }
            }
        }
    }

    // --- epilogue ---
    __syncthreads();
    float* sc = reinterpret_cast<float*>(smem_raw) + wid * (16 * 68);
    const int col0 = wn * 64;
    const int rl   = lane >> 1;
    const int half = lane & 1;

#pragma unroll
    for (int mi = 0; mi < 2; mi++) {
#pragma unroll
        for (int ni = 0; ni < 4; ni++)
            wmma::store_matrix_sync(sc + ni * 16, acc[mi][ni], 68, wmma::mem_row_major);
        __syncwarp();

        int grow = row0 + wm * 32 + mi * 16 + rl;
        if (grow < N_NODES) {
#pragma unroll
            for (int j = 0; j < 8; j++) {
                int c = half * 32 + j * 4;
                float4 v = *reinterpret_cast<const float4*>(sc + rl * 68 + c);
                float4 b4 = *reinterpret_cast<const float4*>(bias + col0 + c);
                v.x += b4.x; v.y += b4.y; v.z += b4.z; v.w += b4.w;
                if (FUSED) {
                    v.x = fmaxf(v.x, 0.f); v.y = fmaxf(v.y, 0.f);
                    v.z = fmaxf(v.z, 0.f); v.w = fmaxf(v.w, 0.f);
                    float4 rr = *reinterpret_cast<const float4*>(A2 + (size_t)grow * DIM + col0 + c);
                    v.x += rr.x; v.y += rr.y; v.z += rr.z; v.w += rr.w;
                }
                *reinterpret_cast<float4*>(out + (size_t)grow * DIM + col0 + c) = v;
            }
        }
        __syncwarp();
    }
}

// ---------------------------------------------------------------------------
// CSR construction: histogram -> hierarchical scan -> fill
// ---------------------------------------------------------------------------
__global__ void zero_deg_kernel() {
    int i = blockIdx.x * blockDim.x + threadIdx.x;
    if (i < N_NODES) g_deg[i] = 0;
}

__global__ void hist_kernel(const int* __restrict__ dst) {
    int e = blockIdx.x * blockDim.x + threadIdx.x;
    if (e < N_EDGES) atomicAdd(&g_deg[dst[e]], 1);
}

__global__ void block_reduce_kernel() {
    __shared__ int sh[256];
    int tid = threadIdx.x;
    int i = blockIdx.x * 256 + tid;
    int v = (i < N_NODES) ? g_deg[i] : 0;
    sh[tid] = v;
    __syncthreads();
#pragma unroll
    for (int s = 128; s > 0; s >>= 1) {
        if (tid < s) sh[tid] += sh[tid + s];
        __syncthreads();
    }
    if (tid == 0) g_bsum[blockIdx.x] = sh[0];
}

__global__ void scan_bsum_kernel() {
    __shared__ int sh[256];
    int tid = threadIdx.x;
    int v = (tid < NBLK_NODE) ? g_bsum[tid] : 0;
    sh[tid] = v;
    __syncthreads();
#pragma unroll
    for (int off = 1; off < 256; off <<= 1) {
        int t = (tid >= off) ? sh[tid - off] : 0;
        __syncthreads();
        sh[tid] += t;
        __syncthreads();
    }
    if (tid < NBLK_NODE) g_bbase[tid] = sh[tid] - v;  // exclusive
    if (tid == 0) g_off[N_NODES] = N_EDGES;
}

__global__ void scan_write_kernel() {
    __shared__ int sh[256];
    int tid = threadIdx.x;
    int i = blockIdx.x * 256 + tid;
    int v = (i < N_NODES) ? g_deg[i] : 0;
    sh[tid] = v;
    __syncthreads();
#pragma unroll
    for (int off = 1; off < 256; off <<= 1) {
        int t = (tid >= off) ? sh[tid - off] : 0;
        __syncthreads();
        sh[tid] += t;
        __syncthreads();
    }
    if (i < N_NODES) {
        int o = g_bbase[blockIdx.x] + sh[tid] - v;
        g_off[i] = o;
        g_cur[i] = o;
    }
}

__global__ void fill_kernel(const int* __restrict__ src, const int* __restrict__ dst) {
    int e = blockIdx.x * blockDim.x + threadIdx.x;
    if (e < N_EDGES) {
        int d = dst[e];
        int pos = atomicAdd(&g_cur[d], 1);
        g_srcs[pos] = src[e];
    }
}

// ---------------------------------------------------------------------------
// Aggregate: one warp per node; coalesced index load + shfl broadcast,
// 4 neighbor rows in flight (MLP=4).
// ---------------------------------------------------------------------------
__global__ __launch_bounds__(256) void aggregate_kernel() {
    const int node = (blockIdx.x * blockDim.x + threadIdx.x) >> 5;
    const int lane = threadIdx.x & 31;
    if (node >= N_NODES) return;
    const int s = g_off[node];
    const int e = g_off[node + 1];
    const float4* __restrict__ h4 = reinterpret_cast<const float4*>(g_h);
    float4 acc = make_float4(0.f, 0.f, 0.f, 0.f);
    int i = s;
    while (i < e) {
        int cnt = min(e - i, 32);
        int idx = (lane < cnt) ? g_srcs[i + lane] : 0;
        int j = 0;
        for (; j + 4 <= cnt; j += 4) {
            int s0 = __shfl_sync(0xFFFFFFFFu, idx, j);
            int s1 = __shfl_sync(0xFFFFFFFFu, idx, j + 1);
            int s2 = __shfl_sync(0xFFFFFFFFu, idx, j + 2);
            int s3 = __shfl_sync(0xFFFFFFFFu, idx, j + 3);
            float4 v0 = h4[(size_t)s0 * 32 + lane];
            float4 v1 = h4[(size_t)s1 * 32 + lane];
            float4 v2 = h4[(size_t)s2 * 32 + lane];
            float4 v3 = h4[(size_t)s3 * 32 + lane];
            acc.x += (v0.x + v1.x) + (v2.x + v3.x);
            acc.y += (v0.y + v1.y) + (v2.y + v3.y);
            acc.z += (v0.z + v1.z) + (v2.z + v3.z);
            acc.w += (v0.w + v1.w) + (v2.w + v3.w);
        }
        for (; j < cnt; j++) {
            int s0 = __shfl_sync(0xFFFFFFFFu, idx, j);
            float4 v0 = h4[(size_t)s0 * 32 + lane];
            acc.x += v0.x; acc.y += v0.y; acc.z += v0.z; acc.w += v0.w;
        }
        i += cnt;
    }
    reinterpret_cast<float4*>(g_agg)[(size_t)node * 32 + lane] = acc;
}

// ---------------------------------------------------------------------------
// Launch (single stream — proven fastest topology)
// ---------------------------------------------------------------------------
extern "C" void kernel_launch(void* const* d_in, const int* in_sizes, int n_in,
                              void* d_out, int out_size)
{
    const float* x       = (const float*)d_in[0];
    const int*   ei      = (const int*)  d_in[1];
    const float* in_fc_w = (const float*)d_in[2];
    const float* in_fc_b = (const float*)d_in[3];
    const float* w_rel   = (const float*)d_in[4];
    const float* b_rel   = (const float*)d_in[5];
    const float* w_root  = (const float*)d_in[6];
    float* out = (float*)d_out;

    const int* src = ei;
    const int* dst = ei + N_EDGES;

    float* h_ptr;   cudaGetSymbolAddress((void**)&h_ptr, g_h);
    float* agg_ptr; cudaGetSymbolAddress((void**)&agg_ptr, g_agg);

    const int GEMM_BLOCKS = (N_NODES + 127) / 128;       // 391
    const int EDGE_BLOCKS = (N_EDGES + 255) / 256;       // 3125
    const int AGG_BLOCKS  = (N_NODES * 32 + 255) / 256;  // 1 warp per node

    // CSR build
    zero_deg_kernel<<<NBLK_NODE, 256>>>();
    hist_kernel<<<EDGE_BLOCKS, 256>>>(dst);
    block_reduce_kernel<<<NBLK_NODE, 256>>>();
    scan_bsum_kernel<<<1, 256>>>();
    scan_write_kernel<<<NBLK_NODE, 256>>>();
    fill_kernel<<<EDGE_BLOCKS, 256>>>(src, dst);

    // in_fc: h = x @ in_fc_w + b
    gemm_wmma_kernel<false><<<GEMM_BLOCKS, 256>>>(
        x, in_fc_w, nullptr, nullptr, in_fc_b, h_ptr);

    // 3 GraphConv layers: out = relu(agg@w_rel + h@w_root + b) + h
    for (int l = 0; l < NLAYERS; l++) {
        aggregate_kernel<<<AGG_BLOCKS, 256>>>();
        float* dst_buf = (l == NLAYERS - 1) ? out : h_ptr;
        gemm_wmma_kernel<true><<<GEMM_BLOCKS, 256>>>(
            agg_ptr, w_rel + (size_t)l * DIM * DIM,
            h_ptr,   w_root + (size_t)l * DIM * DIM,
            b_rel + (size_t)l * DIM, dst_buf);
    }
}